// round 7
// baseline (speedup 1.0000x reference)
#include <cuda_runtime.h>
#include <cstdint>

#define BN 512     // batch (i and j)
#define HH 512     // hidden
#define DX 128     // dim_x = dim_y

// Scratch (device globals). K is split into two halves; main adds them.
__device__ __align__(16) float hxT_g[2 * HH * BN];   // [kc][h][i]
__device__ __align__(16) float nhyT_g[2 * HH * BN];  // [kc][h][j] (negated)
__device__ __align__(16) float part_g[8 * BN * BN];  // per-h-chunk partials

#define UNPACK2(lo, hi, in) \
    asm("mov.b64 {%0, %1}, %2;" : "=f"(lo), "=f"(hi) : "l"(in))
#define FMA2(acc, a, b) \
    asm("fma.rn.f32x2 %0, %1, %2, %0;" : "+l"(acc) : "l"(a), "l"(b))
// 16B shared load straight into two packed fp32x2 (aligned reg pairs, no movs)
#define LDS_V2U64(d0, d1, saddr) \
    asm volatile("ld.shared.v2.u64 {%0, %1}, [%2];" \
                 : "=l"(d0), "=l"(d1) : "r"(saddr))

// ---------------------------------------------------------------------------
// prep: one K-half (64) of the stacked GEMM [x;y] @ W1, transposed outputs.
//   x rows:  hxT_g[kc][h][r]  =  x @ W1[kc*64 : kc*64+64]   (+b1 in kc==0)
//   y rows:  nhyT_g[kc][h][r] = -(y @ W1[128+kc*64 : ...])
// grid (16 r-tiles, 8 h-tiles, 2 kc) = 256 blocks, 256 threads.
// tile 64r x 64h x 64k, thread 4r x 4h. FMA2 inner loop, W pre-duplicated in
// smem so there are ZERO pack movs: 3 LDS.128 + 8 FMA2 per k.
// ---------------------------------------------------------------------------
__global__ void __launch_bounds__(256, 2) prep_kernel(
    const float* __restrict__ x, const float* __restrict__ y,
    const float* __restrict__ W1, const float* __restrict__ b1)
{
    __shared__ float As[64][64];    // [k][r]
    __shared__ float Wd[64][128];   // [k][2h] duplicated pairs

    const bool isY = (blockIdx.x >= 8);
    const int r0   = (isY ? (blockIdx.x - 8) : blockIdx.x) * 64;
    const int h0   = blockIdx.y * 64;
    const int kc   = blockIdx.z;
    const float* __restrict__ in = isY ? y : x;
    const int wrow0 = (isY ? DX : 0) + kc * 64;

    const int tid = threadIdx.x;
    const int tr  = tid & 15;    // r frag = tr*4
    const int th  = tid >> 4;    // 0..15 : h frag = th*4

    uint64_t acc[4][2] = {};     // [h][r-pair] packed fp32x2

    // stage input tile transposed: As[k][r]
    const int sr = tid & 63;         // row
    const int sg = tid >> 6;         // k-group (0..3)
    #pragma unroll
    for (int m = 0; m < 4; m++) {
        int k0 = sg * 16 + m * 4;
        float4 v = *(const float4*)(in + (r0 + sr) * DX + kc * 64 + k0);
        As[k0 + 0][sr] = v.x;
        As[k0 + 1][sr] = v.y;
        As[k0 + 2][sr] = v.z;
        As[k0 + 3][sr] = v.w;
    }
    // stage W1 tile duplicated: Wd[k][2h], Wd[k][2h+1] = W1[wrow0+k][h0+h]
    #pragma unroll
    for (int m = 0; m < 4; m++) {
        int f = tid + 256 * m;          // float4 index 0..1023
        int k = f >> 4, q = f & 15;
        float4 w = *(const float4*)(W1 + (wrow0 + k) * HH + h0 + q * 4);
        float4 d0 = {w.x, w.x, w.y, w.y};
        float4 d1 = {w.z, w.z, w.w, w.w};
        *(float4*)&Wd[k][q * 8]     = d0;
        *(float4*)&Wd[k][q * 8 + 4] = d1;
    }
    __syncthreads();

    const uint32_t aAddr = (uint32_t)__cvta_generic_to_shared(&As[0][tr * 4]);
    const uint32_t wAddr = (uint32_t)__cvta_generic_to_shared(&Wd[0][th * 8]);

    // inner: per k, 3x ld.shared.v2.u64 + 8 FMA2 (16 MACs). Batch 2 k-steps.
    #pragma unroll 4
    for (int kb = 0; kb < 32; kb++) {
        uint64_t a01a, a23a, a01b, a23b;
        uint64_t w01a, w23a, w45a, w67a, w01b, w23b, w45b, w67b;
        const int k = kb * 2;
        LDS_V2U64(a01a, a23a, aAddr + (k    ) * 256);
        LDS_V2U64(a01b, a23b, aAddr + (k + 1) * 256);
        LDS_V2U64(w01a, w23a, wAddr + (k    ) * 512);
        LDS_V2U64(w45a, w67a, wAddr + (k    ) * 512 + 16);
        LDS_V2U64(w01b, w23b, wAddr + (k + 1) * 512);
        LDS_V2U64(w45b, w67b, wAddr + (k + 1) * 512 + 16);

        FMA2(acc[0][0], a01a, w01a); FMA2(acc[0][1], a23a, w01a);
        FMA2(acc[1][0], a01a, w23a); FMA2(acc[1][1], a23a, w23a);
        FMA2(acc[2][0], a01a, w45a); FMA2(acc[2][1], a23a, w45a);
        FMA2(acc[3][0], a01a, w67a); FMA2(acc[3][1], a23a, w67a);

        FMA2(acc[0][0], a01b, w01b); FMA2(acc[0][1], a23b, w01b);
        FMA2(acc[1][0], a01b, w23b); FMA2(acc[1][1], a23b, w23b);
        FMA2(acc[2][0], a01b, w45b); FMA2(acc[2][1], a23b, w45b);
        FMA2(acc[3][0], a01b, w67b); FMA2(acc[3][1], a23b, w67b);
    }

    float* outg = (isY ? nhyT_g : hxT_g) + kc * (HH * BN);
    #pragma unroll
    for (int c = 0; c < 4; c++) {
        const int h = h0 + th * 4 + c;
        float v0, v1, v2, v3;
        UNPACK2(v0, v1, acc[c][0]);
        UNPACK2(v2, v3, acc[c][1]);
        float4 o;
        if (isY) {
            o.x = -v0; o.y = -v1; o.z = -v2; o.w = -v3;
        } else {
            float bb = (kc == 0) ? b1[h] : 0.f;
            o.x = v0 + bb; o.y = v1 + bb; o.z = v2 + bb; o.w = v3 + bb;
        }
        *(float4*)(outg + h * BN + r0 + tr * 4) = o;
    }
}

// ---------------------------------------------------------------------------
// main: partial[z][i,j] = sum_{h in chunk z} max(hx[i,h], -hy[j,h])*w2[h]
//                         + sum_{h in chunk z} hy[j,h]*w2[h]        (gy part)
// grid (4 j-tiles, 8 i-tiles, 8 h-chunks) = 256 blocks, 256 threads.
// block tile 64i x 128j x 64h; thread tile 4i x 8j (j split {lo, hi+64}).
// staging adds the two K-halves produced by prep. Loads batched per h-pair.
// ---------------------------------------------------------------------------
__global__ void __launch_bounds__(256, 3) main_kernel(const float* __restrict__ W2)
{
    __shared__ float Axs[32][64];    // [h][i]
    __shared__ float Bys[32][128];   // [h][j] (negated hy)
    __shared__ float w2s[32];
    __shared__ float gybuf[2][128];

    const int j0 = blockIdx.x * 128;
    const int i0 = blockIdx.y * 64;
    const int hb = blockIdx.z * 64;

    const int tid = threadIdx.x;
    const int ti  = tid >> 4;    // 0..15 : i frag = ti*4
    const int tj  = tid & 15;    // j frags = tj*4 and 64 + tj*4
    const int gq  = tid >> 7;    // 0..1 gy strip
    const int gj  = tid & 127;   // gy j index

    float acc[4][8] = {};
    float gyp = 0.f;

    for (int s = 0; s < 2; s++) {
        const int h0 = hb + s * 32;
        __syncthreads();
        // stage hx chunk [32h x 64i] = half0 + half1
        #pragma unroll
        for (int m = 0; m < 2; m++) {
            int t = tid + 256 * m;          // 0..511
            int h = t >> 4, q = t & 15;
            const float* base = hxT_g + (h0 + h) * BN + i0 + q * 4;
            float4 u = *(const float4*)base;
            float4 v = *(const float4*)(base + HH * BN);
            u.x += v.x; u.y += v.y; u.z += v.z; u.w += v.w;
            *(float4*)&Axs[h][q * 4] = u;
        }
        // stage -hy chunk [32h x 128j] = half0 + half1
        #pragma unroll
        for (int m = 0; m < 4; m++) {
            int t = tid + 256 * m;          // 0..1023
            int h = t >> 5, q = t & 31;
            const float* base = nhyT_g + (h0 + h) * BN + j0 + q * 4;
            float4 u = *(const float4*)base;
            float4 v = *(const float4*)(base + HH * BN);
            u.x += v.x; u.y += v.y; u.z += v.z; u.w += v.w;
            *(float4*)&Bys[h][q * 4] = u;
        }
        if (tid < 32) w2s[tid] = W2[h0 + tid];
        __syncthreads();

        // batched loads per h-pair: 6 independent LDS.128 + 1 LDS.64, then math
        #pragma unroll 2
        for (int hp = 0; hp < 16; hp++) {
            const int h = hp * 2;
            float4 a0  = *(const float4*)&Axs[h][ti * 4];
            float4 a1  = *(const float4*)&Axs[h + 1][ti * 4];
            float4 p0  = *(const float4*)&Bys[h][tj * 4];
            float4 p1  = *(const float4*)&Bys[h][64 + tj * 4];
            float4 q0  = *(const float4*)&Bys[h + 1][tj * 4];
            float4 q1  = *(const float4*)&Bys[h + 1][64 + tj * 4];
            float2 w   = *(const float2*)&w2s[h];

            float av0[4] = {a0.x, a0.y, a0.z, a0.w};
            float bv0[8] = {p0.x, p0.y, p0.z, p0.w, p1.x, p1.y, p1.z, p1.w};
            #pragma unroll
            for (int r = 0; r < 4; r++)
                #pragma unroll
                for (int c = 0; c < 8; c++)
                    acc[r][c] = fmaf(fmaxf(av0[r], bv0[c]), w.x, acc[r][c]);

            float av1[4] = {a1.x, a1.y, a1.z, a1.w};
            float bv1[8] = {q0.x, q0.y, q0.z, q0.w, q1.x, q1.y, q1.z, q1.w};
            #pragma unroll
            for (int r = 0; r < 4; r++)
                #pragma unroll
                for (int c = 0; c < 8; c++)
                    acc[r][c] = fmaf(fmaxf(av1[r], bv1[c]), w.y, acc[r][c]);
        }

        // gy partial: strip gq covers h = gq*16 .. gq*16+15 of this stage
        #pragma unroll
        for (int hh = 0; hh < 16; hh++) {
            int h = gq * 16 + hh;
            gyp = fmaf(Bys[h][gj], w2s[h], gyp);   // accumulates -(hy*w2)
        }
    }

    __syncthreads();
    gybuf[gq][gj] = gyp;
    __syncthreads();

    float gyv[8];
    #pragma unroll
    for (int c = 0; c < 8; c++) {
        int jl = (c < 4) ? (tj * 4 + c) : (64 + tj * 4 + (c - 4));
        gyv[c] = -(gybuf[0][jl] + gybuf[1][jl]);
    }

    float* p = part_g + blockIdx.z * (BN * BN);
    #pragma unroll
    for (int r = 0; r < 4; r++) {
        float4 o0, o1;
        o0.x = acc[r][0] + gyv[0];
        o0.y = acc[r][1] + gyv[1];
        o0.z = acc[r][2] + gyv[2];
        o0.w = acc[r][3] + gyv[3];
        o1.x = acc[r][4] + gyv[4];
        o1.y = acc[r][5] + gyv[5];
        o1.z = acc[r][6] + gyv[6];
        o1.w = acc[r][7] + gyv[7];
        const int row = i0 + ti * 4 + r;
        *(float4*)(p + row * BN + j0 + tj * 4) = o0;
        *(float4*)(p + row * BN + j0 + 64 + tj * 4) = o1;
    }
}

// ---------------------------------------------------------------------------
// reduce: out = sum of 8 partials + b2
// ---------------------------------------------------------------------------
__global__ void __launch_bounds__(256) reduce_kernel(
    const float* __restrict__ b2, float* __restrict__ out)
{
    int idx = blockIdx.x * 256 + threadIdx.x;     // float4 index, 65536 total
    const float4* p = (const float4*)part_g;
    float4 s = p[idx];
    #pragma unroll
    for (int k = 1; k < 8; k++) {
        float4 v = p[idx + k * 65536];
        s.x += v.x; s.y += v.y; s.z += v.z; s.w += v.w;
    }
    float bb = b2[0];
    s.x += bb; s.y += bb; s.z += bb; s.w += bb;
    ((float4*)out)[idx] = s;
}

// ---------------------------------------------------------------------------
extern "C" void kernel_launch(void* const* d_in, const int* in_sizes, int n_in,
                              void* d_out, int out_size)
{
    const float* x  = (const float*)d_in[0];
    const float* y  = (const float*)d_in[1];
    const float* W1 = (const float*)d_in[2];
    const float* b1 = (const float*)d_in[3];
    const float* W2 = (const float*)d_in[4];
    const float* b2 = (const float*)d_in[5];
    float* out = (float*)d_out;

    prep_kernel<<<dim3(16, 8, 2), 256>>>(x, y, W1, b1);
    main_kernel<<<dim3(4, 8, 8), 256>>>(W2);
    reduce_kernel<<<256, 256>>>(b2, out);
}

// round 8
// speedup vs baseline: 1.4605x; 1.4605x over previous
#include <cuda_runtime.h>
#include <cstdint>

#define BN 512     // batch (i and j)
#define HH 512     // hidden
#define DX 128     // dim_x = dim_y

// Scratch (device globals). K is split into two halves; main adds them.
__device__ __align__(16) float hxT_g[2 * HH * BN];    // [kc][h][i]
__device__ __align__(16) float nhyT_g[2 * HH * BN];   // [kc][h][j] (negated)
__device__ __align__(16) float part_g[16 * BN * BN];  // per-h-chunk partials

// ---------------------------------------------------------------------------
// prep (reverted to R6 scalar version): one K-half (64) of the stacked GEMM
// [x;y] @ W1, transposed outputs.
//   x rows:  hxT_g[kc][h][r]  =  x @ W1[kc*64 : kc*64+64]   (+b1 in kc==0)
//   y rows:  nhyT_g[kc][h][r] = -(y @ W1[128+kc*64 : ...])
// grid (16 r-tiles, 8 h-tiles, 2 kc) = 256 blocks, 256 threads.
// tile 64r x 64h x 64k, thread 4r x 4h. Scalar FFMA, k batched by 4 (MLP=8).
// ---------------------------------------------------------------------------
__global__ void __launch_bounds__(256, 2) prep_kernel(
    const float* __restrict__ x, const float* __restrict__ y,
    const float* __restrict__ W1, const float* __restrict__ b1)
{
    __shared__ float As[64][64];   // [k][r]
    __shared__ float Ws[64][64];   // [k][h]

    const bool isY = (blockIdx.x >= 8);
    const int r0   = (isY ? (blockIdx.x - 8) : blockIdx.x) * 64;
    const int h0   = blockIdx.y * 64;
    const int kc   = blockIdx.z;
    const float* __restrict__ in = isY ? y : x;
    const int wrow0 = (isY ? DX : 0) + kc * 64;

    const int tid = threadIdx.x;
    const int tr  = tid & 15;    // r frag = tr*4
    const int th  = tid >> 4;    // 0..15 : h frag = th*4

    float acc[4][4] = {};        // [h][r]

    // stage input tile transposed: As[k][r]
    const int sr = tid & 63;         // row
    const int sg = tid >> 6;         // k-group (0..3)
    #pragma unroll
    for (int m = 0; m < 4; m++) {
        int k0 = sg * 16 + m * 4;
        float4 v = *(const float4*)(in + (r0 + sr) * DX + kc * 64 + k0);
        As[k0 + 0][sr] = v.x;
        As[k0 + 1][sr] = v.y;
        As[k0 + 2][sr] = v.z;
        As[k0 + 3][sr] = v.w;
    }
    // stage W1 tile [64k x 64h]
    #pragma unroll
    for (int m = 0; m < 4; m++) {
        int f = tid + 256 * m;          // float4 index 0..1023
        int k = f >> 4, q = f & 15;
        *(float4*)&Ws[k][q * 4] =
            *(const float4*)(W1 + (wrow0 + k) * HH + h0 + q * 4);
    }
    __syncthreads();

    // compute: batch 4 k-steps of fragments (8 independent LDS.128), then math
    #pragma unroll 4
    for (int kb = 0; kb < 16; kb++) {
        float4 af[4], wf[4];
        #pragma unroll
        for (int u = 0; u < 4; u++)
            af[u] = *(const float4*)&As[kb * 4 + u][tr * 4];
        #pragma unroll
        for (int u = 0; u < 4; u++)
            wf[u] = *(const float4*)&Ws[kb * 4 + u][th * 4];
        #pragma unroll
        for (int u = 0; u < 4; u++) {
            float av[4] = {af[u].x, af[u].y, af[u].z, af[u].w};
            float wv[4] = {wf[u].x, wf[u].y, wf[u].z, wf[u].w};
            #pragma unroll
            for (int c = 0; c < 4; c++)
                #pragma unroll
                for (int r = 0; r < 4; r++)
                    acc[c][r] = fmaf(wv[c], av[r], acc[c][r]);
        }
    }

    float* outg = (isY ? nhyT_g : hxT_g) + kc * (HH * BN);
    #pragma unroll
    for (int c = 0; c < 4; c++) {
        const int h = h0 + th * 4 + c;
        float4 o;
        if (isY) {
            o.x = -acc[c][0]; o.y = -acc[c][1];
            o.z = -acc[c][2]; o.w = -acc[c][3];
        } else {
            float bb = (kc == 0) ? b1[h] : 0.f;
            o.x = acc[c][0] + bb; o.y = acc[c][1] + bb;
            o.z = acc[c][2] + bb; o.w = acc[c][3] + bb;
        }
        *(float4*)(outg + h * BN + r0 + tr * 4) = o;
    }
}

// ---------------------------------------------------------------------------
// main: partial[z][i,j] = sum_{h in chunk z} max(hx[i,h], -hy[j,h])*w2[h]
//                         + sum_{h in chunk z} hy[j,h]*w2[h]        (gy part)
// grid (4 j-tiles, 4 i-tiles, 16 h-chunks) = 256 blocks, 256 threads.
// block tile 128i x 128j x 32h; thread tile 8i x 8j. ONE smem stage, ONE
// barrier before compute. Small loop body (unroll 2) to stay inside L0 I$.
// staging adds the two K-halves produced by prep.
// ---------------------------------------------------------------------------
__global__ void __launch_bounds__(256, 2) main_kernel(const float* __restrict__ W2)
{
    __shared__ float Axs[32][128];   // [h][i]
    __shared__ float Bys[32][128];   // [h][j] (negated hy)
    __shared__ float w2s[32];
    __shared__ float gybuf[2][128];

    const int j0 = blockIdx.x * 128;
    const int i0 = blockIdx.y * 128;
    const int h0 = blockIdx.z * 32;

    const int tid = threadIdx.x;
    const int ti  = tid >> 4;    // 0..15 : i frag = ti*8
    const int tj  = tid & 15;    // 0..15 : j frag = tj*8

    // stage hx chunk [32h x 128i] = half0 + half1
    #pragma unroll
    for (int m = 0; m < 4; m++) {
        int t = tid + 256 * m;          // float4 idx 0..1023
        int h = t >> 5, q = t & 31;
        const float* base = hxT_g + (h0 + h) * BN + i0 + q * 4;
        float4 u = *(const float4*)base;
        float4 v = *(const float4*)(base + HH * BN);
        u.x += v.x; u.y += v.y; u.z += v.z; u.w += v.w;
        *(float4*)&Axs[h][q * 4] = u;
    }
    // stage -hy chunk [32h x 128j] = half0 + half1
    #pragma unroll
    for (int m = 0; m < 4; m++) {
        int t = tid + 256 * m;
        int h = t >> 5, q = t & 31;
        const float* base = nhyT_g + (h0 + h) * BN + j0 + q * 4;
        float4 u = *(const float4*)base;
        float4 v = *(const float4*)(base + HH * BN);
        u.x += v.x; u.y += v.y; u.z += v.z; u.w += v.w;
        *(float4*)&Bys[h][q * 4] = u;
    }
    if (tid < 32) w2s[tid] = W2[h0 + tid];
    __syncthreads();

    float acc[8][8] = {};

    #pragma unroll 2
    for (int h = 0; h < 32; h++) {
        float4 a0 = *(const float4*)&Axs[h][ti * 8];
        float4 a1 = *(const float4*)&Axs[h][ti * 8 + 4];
        float4 b0 = *(const float4*)&Bys[h][tj * 8];
        float4 b1 = *(const float4*)&Bys[h][tj * 8 + 4];
        const float w = w2s[h];
        float av[8] = {a0.x, a0.y, a0.z, a0.w, a1.x, a1.y, a1.z, a1.w};
        float bv[8] = {b0.x, b0.y, b0.z, b0.w, b1.x, b1.y, b1.z, b1.w};
        #pragma unroll
        for (int r = 0; r < 8; r++)
            #pragma unroll
            for (int c = 0; c < 8; c++)
                acc[r][c] = fmaf(fmaxf(av[r], bv[c]), w, acc[r][c]);
    }

    // gy partial for this chunk: gy_z[j] = -sum_h Bys[h][j]*w2[h]
    {
        const int gq = tid >> 7;     // 0..1
        const int gj = tid & 127;
        float gyp = 0.f;
        #pragma unroll
        for (int hh = 0; hh < 16; hh++) {
            int h = gq * 16 + hh;
            gyp = fmaf(Bys[h][gj], w2s[h], gyp);
        }
        __syncthreads();
        gybuf[gq][gj] = gyp;
    }
    __syncthreads();

    float gyv[8];
    #pragma unroll
    for (int c = 0; c < 8; c++) {
        int jl = tj * 8 + c;
        gyv[c] = -(gybuf[0][jl] + gybuf[1][jl]);
    }

    float* p = part_g + blockIdx.z * (BN * BN);
    #pragma unroll
    for (int r = 0; r < 8; r++) {
        float4 o0, o1;
        o0.x = acc[r][0] + gyv[0];
        o0.y = acc[r][1] + gyv[1];
        o0.z = acc[r][2] + gyv[2];
        o0.w = acc[r][3] + gyv[3];
        o1.x = acc[r][4] + gyv[4];
        o1.y = acc[r][5] + gyv[5];
        o1.z = acc[r][6] + gyv[6];
        o1.w = acc[r][7] + gyv[7];
        const int row = i0 + ti * 8 + r;
        *(float4*)(p + row * BN + j0 + tj * 8) = o0;
        *(float4*)(p + row * BN + j0 + tj * 8 + 4) = o1;
    }
}

// ---------------------------------------------------------------------------
// reduce: out = sum of 16 partials + b2
// ---------------------------------------------------------------------------
__global__ void __launch_bounds__(256) reduce_kernel(
    const float* __restrict__ b2, float* __restrict__ out)
{
    int idx = blockIdx.x * 256 + threadIdx.x;     // float4 index, 65536 total
    const float4* p = (const float4*)part_g;
    float4 s = p[idx];
    #pragma unroll
    for (int k = 1; k < 16; k++) {
        float4 v = p[idx + k * 65536];
        s.x += v.x; s.y += v.y; s.z += v.z; s.w += v.w;
    }
    float bb = b2[0];
    s.x += bb; s.y += bb; s.z += bb; s.w += bb;
    ((float4*)out)[idx] = s;
}

// ---------------------------------------------------------------------------
extern "C" void kernel_launch(void* const* d_in, const int* in_sizes, int n_in,
                              void* d_out, int out_size)
{
    const float* x  = (const float*)d_in[0];
    const float* y  = (const float*)d_in[1];
    const float* W1 = (const float*)d_in[2];
    const float* b1 = (const float*)d_in[3];
    const float* W2 = (const float*)d_in[4];
    const float* b2 = (const float*)d_in[5];
    float* out = (float*)d_out;

    prep_kernel<<<dim3(16, 8, 2), 256>>>(x, y, W1, b1);
    main_kernel<<<dim3(4, 4, 16), 256>>>(W2);
    reduce_kernel<<<256, 256>>>(b2, out);
}

// round 9
// speedup vs baseline: 1.5631x; 1.0703x over previous
#include <cuda_runtime.h>
#include <cstdint>

#define BN 512     // batch (i and j)
#define HH 512     // hidden
#define DX 128     // dim_x = dim_y

// Scratch (device globals). K is split into two halves; main adds them.
__device__ __align__(16) float hxT_g[2 * HH * BN];    // [kc][h][i]
__device__ __align__(16) float nhyT_g[2 * HH * BN];   // [kc][h][j] (negated)
__device__ __align__(16) float part_g[16 * BN * BN];  // per-h-chunk partials

// ---------------------------------------------------------------------------
// prep: one K-half (64) of the stacked GEMM [x;y] @ W1, transposed outputs.
//   x rows:  hxT_g[kc][h][r]  =  x @ W1[kc*64 : kc*64+64]   (+b1 in kc==0)
//   y rows:  nhyT_g[kc][h][r] = -(y @ W1[128+kc*64 : ...])
// grid (16 r-tiles, 8 h-tiles, 2 kc) = 256 blocks, 256 threads.
// tile 64r x 64h x 64k, thread 4r x 4h. Scalar FFMA, k batched by 4 (MLP=8).
// ---------------------------------------------------------------------------
__global__ void __launch_bounds__(256, 3) prep_kernel(
    const float* __restrict__ x, const float* __restrict__ y,
    const float* __restrict__ W1, const float* __restrict__ b1)
{
    __shared__ float As[64][64];   // [k][r]
    __shared__ float Ws[64][64];   // [k][h]

    const bool isY = (blockIdx.x >= 8);
    const int r0   = (isY ? (blockIdx.x - 8) : blockIdx.x) * 64;
    const int h0   = blockIdx.y * 64;
    const int kc   = blockIdx.z;
    const float* __restrict__ in = isY ? y : x;
    const int wrow0 = (isY ? DX : 0) + kc * 64;

    const int tid = threadIdx.x;
    const int tr  = tid & 15;    // r frag = tr*4
    const int th  = tid >> 4;    // 0..15 : h frag = th*4

    float acc[4][4] = {};        // [h][r]

    // stage input tile transposed: As[k][r]
    const int sr = tid & 63;         // row
    const int sg = tid >> 6;         // k-group (0..3)
    #pragma unroll
    for (int m = 0; m < 4; m++) {
        int k0 = sg * 16 + m * 4;
        float4 v = *(const float4*)(in + (r0 + sr) * DX + kc * 64 + k0);
        As[k0 + 0][sr] = v.x;
        As[k0 + 1][sr] = v.y;
        As[k0 + 2][sr] = v.z;
        As[k0 + 3][sr] = v.w;
    }
    // stage W1 tile [64k x 64h]
    #pragma unroll
    for (int m = 0; m < 4; m++) {
        int f = tid + 256 * m;          // float4 index 0..1023
        int k = f >> 4, q = f & 15;
        *(float4*)&Ws[k][q * 4] =
            *(const float4*)(W1 + (wrow0 + k) * HH + h0 + q * 4);
    }
    __syncthreads();

    // compute: batch 4 k-steps of fragments (8 independent LDS.128), then math
    #pragma unroll 4
    for (int kb = 0; kb < 16; kb++) {
        float4 af[4], wf[4];
        #pragma unroll
        for (int u = 0; u < 4; u++)
            af[u] = *(const float4*)&As[kb * 4 + u][tr * 4];
        #pragma unroll
        for (int u = 0; u < 4; u++)
            wf[u] = *(const float4*)&Ws[kb * 4 + u][th * 4];
        #pragma unroll
        for (int u = 0; u < 4; u++) {
            float av[4] = {af[u].x, af[u].y, af[u].z, af[u].w};
            float wv[4] = {wf[u].x, wf[u].y, wf[u].z, wf[u].w};
            #pragma unroll
            for (int c = 0; c < 4; c++)
                #pragma unroll
                for (int r = 0; r < 4; r++)
                    acc[c][r] = fmaf(wv[c], av[r], acc[c][r]);
        }
    }

    float* outg = (isY ? nhyT_g : hxT_g) + kc * (HH * BN);
    #pragma unroll
    for (int c = 0; c < 4; c++) {
        const int h = h0 + th * 4 + c;
        float4 o;
        if (isY) {
            o.x = -acc[c][0]; o.y = -acc[c][1];
            o.z = -acc[c][2]; o.w = -acc[c][3];
        } else {
            float bb = (kc == 0) ? b1[h] : 0.f;
            o.x = acc[c][0] + bb; o.y = acc[c][1] + bb;
            o.z = acc[c][2] + bb; o.w = acc[c][3] + bb;
        }
        *(float4*)(outg + h * BN + r0 + tr * 4) = o;
    }
}

// ---------------------------------------------------------------------------
// main: partial[z][i,j] = sum_{h in chunk z} max(hx[i,h], -hy[j,h])*w2[h]
//                         + sum_{h in chunk z} hy[j,h]*w2[h]        (gy part)
// grid (4 j-tiles, 4 i-tiles, 16 h-chunks) = 256 blocks, 256 threads.
// block tile 128i x 128j x 32h; thread tile 8i x 8j with SPLIT fragments
// (4+4 at distance 64 in both i and j) -> conflict-free LDS.128 phases.
// ONE smem stage, ONE barrier before compute.
// ---------------------------------------------------------------------------
__global__ void __launch_bounds__(256, 2) main_kernel(const float* __restrict__ W2)
{
    __shared__ float Axs[32][128];   // [h][i]
    __shared__ float Bys[32][128];   // [h][j] (negated hy)
    __shared__ float w2s[32];
    __shared__ float gybuf[2][128];

    const int j0 = blockIdx.x * 128;
    const int i0 = blockIdx.y * 128;
    const int h0 = blockIdx.z * 32;

    const int tid = threadIdx.x;
    const int ti  = tid >> 4;    // 0..15 : i frags = ti*4 and 64+ti*4
    const int tj  = tid & 15;    // 0..15 : j frags = tj*4 and 64+tj*4

    // stage hx chunk [32h x 128i] = half0 + half1
    #pragma unroll
    for (int m = 0; m < 4; m++) {
        int t = tid + 256 * m;          // float4 idx 0..1023
        int h = t >> 5, q = t & 31;
        const float* base = hxT_g + (h0 + h) * BN + i0 + q * 4;
        float4 u = *(const float4*)base;
        float4 v = *(const float4*)(base + HH * BN);
        u.x += v.x; u.y += v.y; u.z += v.z; u.w += v.w;
        *(float4*)&Axs[h][q * 4] = u;
    }
    // stage -hy chunk [32h x 128j] = half0 + half1
    #pragma unroll
    for (int m = 0; m < 4; m++) {
        int t = tid + 256 * m;
        int h = t >> 5, q = t & 31;
        const float* base = nhyT_g + (h0 + h) * BN + j0 + q * 4;
        float4 u = *(const float4*)base;
        float4 v = *(const float4*)(base + HH * BN);
        u.x += v.x; u.y += v.y; u.z += v.z; u.w += v.w;
        *(float4*)&Bys[h][q * 4] = u;
    }
    if (tid < 32) w2s[tid] = W2[h0 + tid];
    __syncthreads();

    float acc[8][8] = {};

    #pragma unroll 2
    for (int h = 0; h < 32; h++) {
        float4 a0 = *(const float4*)&Axs[h][ti * 4];
        float4 a1 = *(const float4*)&Axs[h][64 + ti * 4];
        float4 b0 = *(const float4*)&Bys[h][tj * 4];
        float4 b1 = *(const float4*)&Bys[h][64 + tj * 4];
        const float w = w2s[h];
        float av[8] = {a0.x, a0.y, a0.z, a0.w, a1.x, a1.y, a1.z, a1.w};
        float bv[8] = {b0.x, b0.y, b0.z, b0.w, b1.x, b1.y, b1.z, b1.w};
        #pragma unroll
        for (int r = 0; r < 8; r++)
            #pragma unroll
            for (int c = 0; c < 8; c++)
                acc[r][c] = fmaf(fmaxf(av[r], bv[c]), w, acc[r][c]);
    }

    // gy partial for this chunk: gy_z[j] = -sum_h Bys[h][j]*w2[h]
    {
        const int gq = tid >> 7;     // 0..1
        const int gj = tid & 127;
        float gyp = 0.f;
        #pragma unroll
        for (int hh = 0; hh < 16; hh++) {
            int h = gq * 16 + hh;
            gyp = fmaf(Bys[h][gj], w2s[h], gyp);
        }
        __syncthreads();
        gybuf[gq][gj] = gyp;
    }
    __syncthreads();

    float gyv[8];
    #pragma unroll
    for (int c = 0; c < 8; c++) {
        int jl = (c < 4) ? (tj * 4 + c) : (64 + tj * 4 + (c - 4));
        gyv[c] = -(gybuf[0][jl] + gybuf[1][jl]);
    }

    float* p = part_g + blockIdx.z * (BN * BN);
    #pragma unroll
    for (int r = 0; r < 8; r++) {
        const int row = i0 + ((r < 4) ? (ti * 4 + r) : (64 + ti * 4 + r - 4));
        float4 o0, o1;
        o0.x = acc[r][0] + gyv[0];
        o0.y = acc[r][1] + gyv[1];
        o0.z = acc[r][2] + gyv[2];
        o0.w = acc[r][3] + gyv[3];
        o1.x = acc[r][4] + gyv[4];
        o1.y = acc[r][5] + gyv[5];
        o1.z = acc[r][6] + gyv[6];
        o1.w = acc[r][7] + gyv[7];
        *(float4*)(p + row * BN + j0 + tj * 4) = o0;
        *(float4*)(p + row * BN + j0 + 64 + tj * 4) = o1;
    }
}

// ---------------------------------------------------------------------------
// reduce: out = sum of 16 partials + b2
// ---------------------------------------------------------------------------
__global__ void __launch_bounds__(256) reduce_kernel(
    const float* __restrict__ b2, float* __restrict__ out)
{
    int idx = blockIdx.x * 256 + threadIdx.x;     // float4 index, 65536 total
    const float4* p = (const float4*)part_g;
    float4 s = p[idx];
    #pragma unroll
    for (int k = 1; k < 16; k++) {
        float4 v = p[idx + k * 65536];
        s.x += v.x; s.y += v.y; s.z += v.z; s.w += v.w;
    }
    float bb = b2[0];
    s.x += bb; s.y += bb; s.z += bb; s.w += bb;
    ((float4*)out)[idx] = s;
}

// ---------------------------------------------------------------------------
extern "C" void kernel_launch(void* const* d_in, const int* in_sizes, int n_in,
                              void* d_out, int out_size)
{
    const float* x  = (const float*)d_in[0];
    const float* y  = (const float*)d_in[1];
    const float* W1 = (const float*)d_in[2];
    const float* b1 = (const float*)d_in[3];
    const float* W2 = (const float*)d_in[4];
    const float* b2 = (const float*)d_in[5];
    float* out = (float*)d_out;

    prep_kernel<<<dim3(16, 8, 2), 256>>>(x, y, W1, b1);
    main_kernel<<<dim3(4, 4, 16), 256>>>(W2);
    reduce_kernel<<<256, 256>>>(b2, out);
}

// round 10
// speedup vs baseline: 1.5857x; 1.0145x over previous
#include <cuda_runtime.h>
#include <cstdint>

#define BN 512     // batch (i and j)
#define HH 512     // hidden
#define DX 128     // dim_x = dim_y

// Scratch (device globals). K is split into two halves; main adds them.
__device__ __align__(16) float hxT_g[2 * HH * BN];   // [kc][h][i]
__device__ __align__(16) float nhyT_g[2 * HH * BN];  // [kc][h][j] (negated)
__device__ __align__(16) float part_g[8 * BN * BN];  // per-h-chunk partials

// ---------------------------------------------------------------------------
// prep: one K-half (64) of the stacked GEMM [x;y] @ W1, transposed outputs.
//   x rows:  hxT_g[kc][h][r]  =  x @ W1[kc*64 : kc*64+64]   (+b1 in kc==0)
//   y rows:  nhyT_g[kc][h][r] = -(y @ W1[128+kc*64 : ...])
// grid (16 r-tiles, 8 h-tiles, 2 kc) = 256 blocks, 256 threads.
// tile 64r x 64h x 64k, thread 4r x 4h. Scalar FFMA, k batched by 4 (MLP=8).
// ---------------------------------------------------------------------------
__global__ void __launch_bounds__(256, 3) prep_kernel(
    const float* __restrict__ x, const float* __restrict__ y,
    const float* __restrict__ W1, const float* __restrict__ b1)
{
    __shared__ float As[64][64];   // [k][r]
    __shared__ float Ws[64][64];   // [k][h]

    const bool isY = (blockIdx.x >= 8);
    const int r0   = (isY ? (blockIdx.x - 8) : blockIdx.x) * 64;
    const int h0   = blockIdx.y * 64;
    const int kc   = blockIdx.z;
    const float* __restrict__ in = isY ? y : x;
    const int wrow0 = (isY ? DX : 0) + kc * 64;

    const int tid = threadIdx.x;
    const int tr  = tid & 15;    // r frag = tr*4
    const int th  = tid >> 4;    // 0..15 : h frag = th*4

    float acc[4][4] = {};        // [h][r]

    // stage input tile transposed: As[k][r]
    const int sr = tid & 63;         // row
    const int sg = tid >> 6;         // k-group (0..3)
    #pragma unroll
    for (int m = 0; m < 4; m++) {
        int k0 = sg * 16 + m * 4;
        float4 v = *(const float4*)(in + (r0 + sr) * DX + kc * 64 + k0);
        As[k0 + 0][sr] = v.x;
        As[k0 + 1][sr] = v.y;
        As[k0 + 2][sr] = v.z;
        As[k0 + 3][sr] = v.w;
    }
    // stage W1 tile [64k x 64h]
    #pragma unroll
    for (int m = 0; m < 4; m++) {
        int f = tid + 256 * m;          // float4 index 0..1023
        int k = f >> 4, q = f & 15;
        *(float4*)&Ws[k][q * 4] =
            *(const float4*)(W1 + (wrow0 + k) * HH + h0 + q * 4);
    }
    __syncthreads();

    // compute: batch 4 k-steps of fragments (8 independent LDS.128), then math
    #pragma unroll 4
    for (int kb = 0; kb < 16; kb++) {
        float4 af[4], wf[4];
        #pragma unroll
        for (int u = 0; u < 4; u++)
            af[u] = *(const float4*)&As[kb * 4 + u][tr * 4];
        #pragma unroll
        for (int u = 0; u < 4; u++)
            wf[u] = *(const float4*)&Ws[kb * 4 + u][th * 4];
        #pragma unroll
        for (int u = 0; u < 4; u++) {
            float av[4] = {af[u].x, af[u].y, af[u].z, af[u].w};
            float wv[4] = {wf[u].x, wf[u].y, wf[u].z, wf[u].w};
            #pragma unroll
            for (int c = 0; c < 4; c++)
                #pragma unroll
                for (int r = 0; r < 4; r++)
                    acc[c][r] = fmaf(wv[c], av[r], acc[c][r]);
        }
    }

    float* outg = (isY ? nhyT_g : hxT_g) + kc * (HH * BN);
    #pragma unroll
    for (int c = 0; c < 4; c++) {
        const int h = h0 + th * 4 + c;
        float4 o;
        if (isY) {
            o.x = -acc[c][0]; o.y = -acc[c][1];
            o.z = -acc[c][2]; o.w = -acc[c][3];
        } else {
            float bb = (kc == 0) ? b1[h] : 0.f;
            o.x = acc[c][0] + bb; o.y = acc[c][1] + bb;
            o.z = acc[c][2] + bb; o.w = acc[c][3] + bb;
        }
        *(float4*)(outg + h * BN + r0 + tr * 4) = o;
    }
}

// ---------------------------------------------------------------------------
// main: partial[z][i,j] = sum_{h in chunk z} max(hx[i,h], -hy[j,h])*w2[h]
//                         + sum_{h in chunk z} hy[j,h]*w2[h]        (gy part)
// grid (8 j-tiles, 4 i-tiles, 8 h-chunks) = 256 blocks, 256 threads.
// block tile 128i x 64j x 64h; thread tile 8i x 4j with split i fragments
// (ti*4 and 64+ti*4) -> conflict-free LDS.128. ONE smem stage (48 KB), ONE
// barrier before compute. 64h per CTA halves staging/tail relative cost.
// staging adds the two K-halves produced by prep.
// ---------------------------------------------------------------------------
__global__ void __launch_bounds__(256, 2) main_kernel(const float* __restrict__ W2)
{
    __shared__ float Axs[64][128];   // [h][i]
    __shared__ float Bys[64][64];    // [h][j] (negated hy)
    __shared__ float w2s[64];
    __shared__ float gybuf[4][64];

    const int j0 = blockIdx.x * 64;
    const int i0 = blockIdx.y * 128;
    const int h0 = blockIdx.z * 64;

    const int tid = threadIdx.x;
    const int ti  = tid >> 4;    // 0..15 : i frags = ti*4 and 64+ti*4
    const int tj  = tid & 15;    // 0..15 : j frag  = tj*4

    // stage hx chunk [64h x 128i] = half0 + half1 (2048 float4)
    #pragma unroll
    for (int m = 0; m < 8; m++) {
        int t = tid + 256 * m;          // float4 idx 0..2047
        int h = t >> 5, q = t & 31;
        const float* base = hxT_g + (h0 + h) * BN + i0 + q * 4;
        float4 u = *(const float4*)base;
        float4 v = *(const float4*)(base + HH * BN);
        u.x += v.x; u.y += v.y; u.z += v.z; u.w += v.w;
        *(float4*)&Axs[h][q * 4] = u;
    }
    // stage -hy chunk [64h x 64j] = half0 + half1 (1024 float4)
    #pragma unroll
    for (int m = 0; m < 4; m++) {
        int t = tid + 256 * m;          // float4 idx 0..1023
        int h = t >> 4, q = t & 15;
        const float* base = nhyT_g + (h0 + h) * BN + j0 + q * 4;
        float4 u = *(const float4*)base;
        float4 v = *(const float4*)(base + HH * BN);
        u.x += v.x; u.y += v.y; u.z += v.z; u.w += v.w;
        *(float4*)&Bys[h][q * 4] = u;
    }
    if (tid < 64) w2s[tid] = W2[h0 + tid];
    __syncthreads();

    float acc[8][4] = {};

    #pragma unroll 2
    for (int hp = 0; hp < 32; hp++) {
        const int h = hp * 2;
        float2 w = *(const float2*)&w2s[h];

        float4 a0 = *(const float4*)&Axs[h][ti * 4];
        float4 a1 = *(const float4*)&Axs[h][64 + ti * 4];
        float4 b0 = *(const float4*)&Bys[h][tj * 4];
        {
            float av[8] = {a0.x, a0.y, a0.z, a0.w, a1.x, a1.y, a1.z, a1.w};
            float bv[4] = {b0.x, b0.y, b0.z, b0.w};
            #pragma unroll
            for (int r = 0; r < 8; r++)
                #pragma unroll
                for (int c = 0; c < 4; c++)
                    acc[r][c] = fmaf(fmaxf(av[r], bv[c]), w.x, acc[r][c]);
        }
        float4 a2 = *(const float4*)&Axs[h + 1][ti * 4];
        float4 a3 = *(const float4*)&Axs[h + 1][64 + ti * 4];
        float4 b1 = *(const float4*)&Bys[h + 1][tj * 4];
        {
            float av[8] = {a2.x, a2.y, a2.z, a2.w, a3.x, a3.y, a3.z, a3.w};
            float bv[4] = {b1.x, b1.y, b1.z, b1.w};
            #pragma unroll
            for (int r = 0; r < 8; r++)
                #pragma unroll
                for (int c = 0; c < 4; c++)
                    acc[r][c] = fmaf(fmaxf(av[r], bv[c]), w.y, acc[r][c]);
        }
    }

    // gy partial for this chunk: gy_z[j] = -sum_h Bys[h][j]*w2[h]
    {
        const int gq = tid >> 6;     // 0..3 : h strip = gq*16 .. gq*16+15
        const int gj = tid & 63;
        float gyp = 0.f;
        #pragma unroll
        for (int hh = 0; hh < 16; hh++) {
            int h = gq * 16 + hh;
            gyp = fmaf(Bys[h][gj], w2s[h], gyp);
        }
        __syncthreads();
        gybuf[gq][gj] = gyp;
    }
    __syncthreads();

    float gyv[4];
    #pragma unroll
    for (int c = 0; c < 4; c++) {
        int jl = tj * 4 + c;
        gyv[c] = -(gybuf[0][jl] + gybuf[1][jl] + gybuf[2][jl] + gybuf[3][jl]);
    }

    float* p = part_g + blockIdx.z * (BN * BN);
    #pragma unroll
    for (int r = 0; r < 8; r++) {
        const int row = i0 + ((r < 4) ? (ti * 4 + r) : (64 + ti * 4 + r - 4));
        float4 o;
        o.x = acc[r][0] + gyv[0];
        o.y = acc[r][1] + gyv[1];
        o.z = acc[r][2] + gyv[2];
        o.w = acc[r][3] + gyv[3];
        *(float4*)(p + row * BN + j0 + tj * 4) = o;
    }
}

// ---------------------------------------------------------------------------
// reduce: out = sum of 8 partials + b2
// ---------------------------------------------------------------------------
__global__ void __launch_bounds__(256) reduce_kernel(
    const float* __restrict__ b2, float* __restrict__ out)
{
    int idx = blockIdx.x * 256 + threadIdx.x;     // float4 index, 65536 total
    const float4* p = (const float4*)part_g;
    float4 s = p[idx];
    #pragma unroll
    for (int k = 1; k < 8; k++) {
        float4 v = p[idx + k * 65536];
        s.x += v.x; s.y += v.y; s.z += v.z; s.w += v.w;
    }
    float bb = b2[0];
    s.x += bb; s.y += bb; s.z += bb; s.w += bb;
    ((float4*)out)[idx] = s;
}

// ---------------------------------------------------------------------------
extern "C" void kernel_launch(void* const* d_in, const int* in_sizes, int n_in,
                              void* d_out, int out_size)
{
    const float* x  = (const float*)d_in[0];
    const float* y  = (const float*)d_in[1];
    const float* W1 = (const float*)d_in[2];
    const float* b1 = (const float*)d_in[3];
    const float* W2 = (const float*)d_in[4];
    const float* b2 = (const float*)d_in[5];
    float* out = (float*)d_out;

    prep_kernel<<<dim3(16, 8, 2), 256>>>(x, y, W1, b1);
    main_kernel<<<dim3(8, 4, 8), 256>>>(W2);
    reduce_kernel<<<256, 256>>>(b2, out);
}

// round 14
// speedup vs baseline: 1.6812x; 1.0602x over previous
#include <cuda_runtime.h>
#include <cstdint>

#define BN 512     // batch (i and j)
#define HH 512     // hidden
#define DX 128     // dim_x = dim_y

// Scratch (device globals). Full-K prep outputs (no K split).
__device__ __align__(16) float hxT_g[HH * BN];      // [h][i]  = x@W1x + b1
__device__ __align__(16) float nhyT_g[HH * BN];     // [h][j]  = -(y@W1y)
__device__ __align__(16) float part_g[8 * BN * BN]; // per-h-chunk partials

// ---------------------------------------------------------------------------
// TF32 helpers
// ---------------------------------------------------------------------------
__device__ __forceinline__ uint32_t f2tf32(float f) {
    uint32_t r;
    asm("cvt.rna.tf32.f32 %0, %1;" : "=r"(r) : "f"(f));
    return r;
}

#define MMA_TF32(c, a0, a1, a2, a3, b0, b1)                                   \
    asm volatile(                                                             \
        "mma.sync.aligned.m16n8k8.row.col.f32.tf32.tf32.f32 "                 \
        "{%0,%1,%2,%3},{%4,%5,%6,%7},{%8,%9},{%0,%1,%2,%3};"                  \
        : "+f"((c)[0]), "+f"((c)[1]), "+f"((c)[2]), "+f"((c)[3])              \
        : "r"(a0), "r"(a1), "r"(a2), "r"(a3), "r"(b0), "r"(b1))

// smem layout (dynamic): As[64][132] f32, Bhi[128][68] u32, Blo[128][68] u32
#define AP 132
#define BP 68
#define SMEM_A_FLOATS  (64 * AP)            // 8448
#define SMEM_B_WORDS   (128 * BP)           // 8704
#define PREP_SMEM_BYTES ((SMEM_A_FLOATS + 2 * SMEM_B_WORDS) * 4)  // 103424

// ---------------------------------------------------------------------------
// prep (tensor cores, 3xTF32): out = [x;y] @ W1, transposed, full K=128.
//   x blocks: hxT_g[h][r]  =  x @ W1[0:128]   + b1
//   y blocks: nhyT_g[h][r] = -(y @ W1[128:256])
// grid (16 r-tiles, 8 h-tiles) = 128 CTAs, 256 threads (8 warps).
// block tile 64r x 64h x 128k; warp tile 16r x 32h; mma.sync m16n8k8 tf32.
// 3xTF32: C += Ah*Bh + Ah*Bl + Al*Bh  (fp32-grade accuracy).
// ---------------------------------------------------------------------------
__global__ void __launch_bounds__(256, 2) prep_kernel(
    const float* __restrict__ x, const float* __restrict__ y,
    const float* __restrict__ W1, const float* __restrict__ b1)
{
    extern __shared__ float smemf[];
    float*    As  = smemf;                                   // [64][AP]
    uint32_t* Bhi = (uint32_t*)(smemf + SMEM_A_FLOATS);      // [128][BP]
    uint32_t* Blo = Bhi + SMEM_B_WORDS;                      // [128][BP]

    const bool isY = (blockIdx.x >= 8);
    const int r0   = (isY ? (blockIdx.x - 8) : blockIdx.x) * 64;
    const int h0   = blockIdx.y * 64;
    const float* __restrict__ in = isY ? y : x;
    const int wofs = isY ? DX : 0;

    const int tid = threadIdx.x;
    const int wid = tid >> 5;
    const int lane = tid & 31;
    const int gID = lane >> 2;     // 0..7
    const int tig = lane & 3;      // 0..3
    const int rw  = wid & 3;       // r-warp: rows rw*16 .. rw*16+15
    const int hw  = wid >> 2;      // h-warp: cols hw*32 .. hw*32+31

    // ---- stage A raw fp32: As[r][k], pitch AP ----
    #pragma unroll
    for (int m = 0; m < 8; m++) {
        int t = tid + 256 * m;          // float4 idx 0..2047
        int r = t >> 5, q = t & 31;     // q: k-float4 0..31
        float4 v = *(const float4*)(in + (r0 + r) * DX + q * 4);
        *(float4*)&As[r * AP + q * 4] = v;
    }
    // ---- stage B pre-split hi/lo: B[k][h], pitch BP ----
    #pragma unroll
    for (int m = 0; m < 8; m++) {
        int t = tid + 256 * m;          // float4 idx 0..2047
        int k = t >> 4, hq = t & 15;    // 16 float4 per k-row (64 h)
        float4 w = *(const float4*)(W1 + (wofs + k) * HH + h0 + hq * 4);
        uint4 hi, lo;
        hi.x = f2tf32(w.x); lo.x = f2tf32(w.x - __uint_as_float(hi.x));
        hi.y = f2tf32(w.y); lo.y = f2tf32(w.y - __uint_as_float(hi.y));
        hi.z = f2tf32(w.z); lo.z = f2tf32(w.z - __uint_as_float(hi.z));
        hi.w = f2tf32(w.w); lo.w = f2tf32(w.w - __uint_as_float(hi.w));
        *(uint4*)&Bhi[k * BP + hq * 4] = hi;
        *(uint4*)&Blo[k * BP + hq * 4] = lo;
    }
    __syncthreads();

    float acc[4][4] = {};   // 4 n-subtiles x (c0..c3)

    const int rbase = rw * 16;
    const int hbase = hw * 32;

    #pragma unroll 4
    for (int kt = 0; kt < 16; kt++) {
        const int k0 = kt * 8;
        // A fragment (m16 x k8): rows rbase+gID(+8), cols k0+tig(+4)
        float wa0 = As[(rbase + gID) * AP + k0 + tig];
        float wa1 = As[(rbase + gID + 8) * AP + k0 + tig];
        float wa2 = As[(rbase + gID) * AP + k0 + tig + 4];
        float wa3 = As[(rbase + gID + 8) * AP + k0 + tig + 4];
        uint32_t ah0 = f2tf32(wa0), ah1 = f2tf32(wa1);
        uint32_t ah2 = f2tf32(wa2), ah3 = f2tf32(wa3);
        uint32_t al0 = f2tf32(wa0 - __uint_as_float(ah0));
        uint32_t al1 = f2tf32(wa1 - __uint_as_float(ah1));
        uint32_t al2 = f2tf32(wa2 - __uint_as_float(ah2));
        uint32_t al3 = f2tf32(wa3 - __uint_as_float(ah3));

        #pragma unroll
        for (int nt = 0; nt < 4; nt++) {
            const int hb = hbase + nt * 8 + gID;
            uint32_t bh0 = Bhi[(k0 + tig) * BP + hb];
            uint32_t bh1 = Bhi[(k0 + tig + 4) * BP + hb];
            uint32_t bl0 = Blo[(k0 + tig) * BP + hb];
            uint32_t bl1 = Blo[(k0 + tig + 4) * BP + hb];
            MMA_TF32(acc[nt], ah0, ah1, ah2, ah3, bh0, bh1);
            MMA_TF32(acc[nt], ah0, ah1, ah2, ah3, bl0, bl1);
            MMA_TF32(acc[nt], al0, al1, al2, al3, bh0, bh1);
        }
    }

    // epilogue: transposed store out[h][r], bias for x, negate for y
    float* outg = isY ? nhyT_g : hxT_g;
    const int r_g = r0 + rbase + gID;
    #pragma unroll
    for (int nt = 0; nt < 4; nt++) {
        const int hcol = h0 + hbase + nt * 8 + 2 * tig;
        if (isY) {
            outg[hcol * BN + r_g]           = -acc[nt][0];
            outg[(hcol + 1) * BN + r_g]     = -acc[nt][1];
            outg[hcol * BN + r_g + 8]       = -acc[nt][2];
            outg[(hcol + 1) * BN + r_g + 8] = -acc[nt][3];
        } else {
            float bb0 = b1[hcol], bb1 = b1[hcol + 1];
            outg[hcol * BN + r_g]           = acc[nt][0] + bb0;
            outg[(hcol + 1) * BN + r_g]     = acc[nt][1] + bb1;
            outg[hcol * BN + r_g + 8]       = acc[nt][2] + bb0;
            outg[(hcol + 1) * BN + r_g + 8] = acc[nt][3] + bb1;
        }
    }
}

// ---------------------------------------------------------------------------
// main: partial[z][i,j] = sum_{h in chunk z} max(hx[i,h], -hy[j,h])*w2[h]
//                         + sum_{h in chunk z} hy[j,h]*w2[h]        (gy part)
// grid (8 j-tiles, 4 i-tiles, 8 h-chunks) = 256 blocks, 256 threads.
// block tile 128i x 64j x 64h; thread tile 8i x 4j with split i fragments.
// ONE smem stage, ONE barrier before compute. Single-buffer staging.
// ---------------------------------------------------------------------------
__global__ void __launch_bounds__(256, 2) main_kernel(const float* __restrict__ W2)
{
    __shared__ float Axs[64][128];   // [h][i]
    __shared__ float Bys[64][64];    // [h][j] (negated hy)
    __shared__ float w2s[64];
    __shared__ float gybuf[4][64];

    const int j0 = blockIdx.x * 64;
    const int i0 = blockIdx.y * 128;
    const int h0 = blockIdx.z * 64;

    const int tid = threadIdx.x;
    const int ti  = tid >> 4;    // 0..15 : i frags = ti*4 and 64+ti*4
    const int tj  = tid & 15;    // 0..15 : j frag  = tj*4

    // stage hx chunk [64h x 128i]
    #pragma unroll
    for (int m = 0; m < 8; m++) {
        int t = tid + 256 * m;          // float4 idx 0..2047
        int h = t >> 5, q = t & 31;
        *(float4*)&Axs[h][q * 4] =
            *(const float4*)(hxT_g + (h0 + h) * BN + i0 + q * 4);
    }
    // stage -hy chunk [64h x 64j]
    #pragma unroll
    for (int m = 0; m < 4; m++) {
        int t = tid + 256 * m;          // float4 idx 0..1023
        int h = t >> 4, q = t & 15;
        *(float4*)&Bys[h][q * 4] =
            *(const float4*)(nhyT_g + (h0 + h) * BN + j0 + q * 4);
    }
    if (tid < 64) w2s[tid] = W2[h0 + tid];
    __syncthreads();

    float acc[8][4] = {};

    #pragma unroll 2
    for (int hp = 0; hp < 32; hp++) {
        const int h = hp * 2;
        float2 w = *(const float2*)&w2s[h];

        float4 a0 = *(const float4*)&Axs[h][ti * 4];
        float4 a1 = *(const float4*)&Axs[h][64 + ti * 4];
        float4 b0 = *(const float4*)&Bys[h][tj * 4];
        {
            float av[8] = {a0.x, a0.y, a0.z, a0.w, a1.x, a1.y, a1.z, a1.w};
            float bv[4] = {b0.x, b0.y, b0.z, b0.w};
            #pragma unroll
            for (int r = 0; r < 8; r++)
                #pragma unroll
                for (int c = 0; c < 4; c++)
                    acc[r][c] = fmaf(fmaxf(av[r], bv[c]), w.x, acc[r][c]);
        }
        float4 a2 = *(const float4*)&Axs[h + 1][ti * 4];
        float4 a3 = *(const float4*)&Axs[h + 1][64 + ti * 4];
        float4 b1v = *(const float4*)&Bys[h + 1][tj * 4];
        {
            float av[8] = {a2.x, a2.y, a2.z, a2.w, a3.x, a3.y, a3.z, a3.w};
            float bv[4] = {b1v.x, b1v.y, b1v.z, b1v.w};
            #pragma unroll
            for (int r = 0; r < 8; r++)
                #pragma unroll
                for (int c = 0; c < 4; c++)
                    acc[r][c] = fmaf(fmaxf(av[r], bv[c]), w.y, acc[r][c]);
        }
    }

    // gy partial for this chunk: gy_z[j] = -sum_h Bys[h][j]*w2[h]
    {
        const int gq = tid >> 6;     // 0..3 : h strip = gq*16 .. gq*16+15
        const int gj = tid & 63;
        float gyp = 0.f;
        #pragma unroll
        for (int hh = 0; hh < 16; hh++) {
            int h = gq * 16 + hh;
            gyp = fmaf(Bys[h][gj], w2s[h], gyp);
        }
        __syncthreads();
        gybuf[gq][gj] = gyp;
    }
    __syncthreads();

    float gyv[4];
    #pragma unroll
    for (int c = 0; c < 4; c++) {
        int jl = tj * 4 + c;
        gyv[c] = -(gybuf[0][jl] + gybuf[1][jl] + gybuf[2][jl] + gybuf[3][jl]);
    }

    float* p = part_g + blockIdx.z * (BN * BN);
    #pragma unroll
    for (int r = 0; r < 8; r++) {
        const int row = i0 + ((r < 4) ? (ti * 4 + r) : (64 + ti * 4 + r - 4));
        float4 o;
        o.x = acc[r][0] + gyv[0];
        o.y = acc[r][1] + gyv[1];
        o.z = acc[r][2] + gyv[2];
        o.w = acc[r][3] + gyv[3];
        *(float4*)(p + row * BN + j0 + tj * 4) = o;
    }
}

// ---------------------------------------------------------------------------
// reduce: out = sum of 8 partials + b2
// ---------------------------------------------------------------------------
__global__ void __launch_bounds__(256) reduce_kernel(
    const float* __restrict__ b2, float* __restrict__ out)
{
    int idx = blockIdx.x * 256 + threadIdx.x;     // float4 index, 65536 total
    const float4* p = (const float4*)part_g;
    float4 s = p[idx];
    #pragma unroll
    for (int k = 1; k < 8; k++) {
        float4 v = p[idx + k * 65536];
        s.x += v.x; s.y += v.y; s.z += v.z; s.w += v.w;
    }
    float bb = b2[0];
    s.x += bb; s.y += bb; s.z += bb; s.w += bb;
    ((float4*)out)[idx] = s;
}

// ---------------------------------------------------------------------------
extern "C" void kernel_launch(void* const* d_in, const int* in_sizes, int n_in,
                              void* d_out, int out_size)
{
    const float* x  = (const float*)d_in[0];
    const float* y  = (const float*)d_in[1];
    const float* W1 = (const float*)d_in[2];
    const float* b1 = (const float*)d_in[3];
    const float* W2 = (const float*)d_in[4];
    const float* b2 = (const float*)d_in[5];
    float* out = (float*)d_out;

    cudaFuncSetAttribute(prep_kernel,
                         cudaFuncAttributeMaxDynamicSharedMemorySize,
                         PREP_SMEM_BYTES);
    prep_kernel<<<dim3(16, 8), 256, PREP_SMEM_BYTES>>>(x, y, W1, b1);
    main_kernel<<<dim3(8, 4, 8), 256>>>(W2);
    reduce_kernel<<<256, 256>>>(b2, out);
}